// round 17
// baseline (speedup 1.0000x reference)
#include <cuda_runtime.h>
#include <cfloat>

#define Bn 512
#define Tn 512
#define Kn 64
#define PD 8  // potentials prefetch ring depth (registers, float2 slots)

// Monotone float <-> uint order-preserving map (finite floats).
__device__ __forceinline__ unsigned fmap(float f) {
    const int i = __float_as_int(f);
    return (unsigned)(i ^ ((i >> 31) | 0x80000000));
}
__device__ __forceinline__ float funmap(unsigned u) {
    const int s = ~((int)u >> 31);
    return __int_as_float((int)(u ^ (0x80000000u | (unsigned)s)));
}

// ---------------------------------------------------------------------------
// Exact full 64-candidate scan (redo / general path), even/odd ownership.
// First max wins (ascending strict >).
// ---------------------------------------------------------------------------
__device__ __noinline__ void full_scan64(
    float a_ev, float a_od, const float2* trans2, int l,
    float& best0, float& best1, int& bi0, int& bi1)
{
    float b0 = -FLT_MAX, b1 = -FLT_MAX;
    int x0 = 0, x1 = 0;
#pragma unroll 4
    for (int i = 0; i < Kn; i++) {
        const float asel = (i & 1) ? a_od : a_ev;
        const float av = __shfl_sync(0xffffffffu, asel, i >> 1);
        const float2 tv = trans2[i * 32 + l];
        const float s0 = av + tv.x, s1 = av + tv.y;
        const bool g0 = s0 > b0; b0 = g0 ? s0 : b0; x0 = g0 ? i : x0;
        const bool g1 = s1 > b1; b1 = g1 ? s1 : b1; x1 = g1 ? i : x1;
    }
    best0 = b0; best1 = b1; bi0 = x0; bi1 = x1;
}

// Candidate fetch: alpha[i] lives in lane i>>1, component i&1 (i uniform).
#define FETCH(i_, se_, so_)                                                 \
    {                                                                       \
        const float asel_ = ((i_) & 1) ? a.y : a.x;                         \
        const float avv_ = __shfl_sync(0xffffffffu, asel_, (i_) >> 1);      \
        const float2 tv_ = trans2[(i_) * 32 + l];                           \
        se_ = avv_ + tv_.x;                                                 \
        so_ = avv_ + tv_.y;                                                 \
    }

// One DP step (speculative fast path). Ring slot S_ is compile-time.
// Even/odd split extraction, 3-deep per half (parallel chains), NO merge:
// per-half FMNMX trees + per-half ordered recovery + cross-half min-select
// gives smallest tag among value-ties == jnp.argmax first-max (bit-exact).
// Fallback fires only for >=4 candidates in one half (rare), index-aware.
#define STEP_F(T_, S_)                                                       \
    {                                                                        \
        const int t_ = (T_);                                                 \
        const float2 p_ = pr[S_];                                            \
        {                                                                    \
            const int tp_ = t_ + PD;                                         \
            const int tl_ = (tp_ <= Tn - 1) ? tp_ : (Tn - 1);                \
            const float2 n_ = pb2[tl_ * 32 + l];  /* ONE LDG.64 */           \
            pr[S_] = n_;                                                     \
            if (tp_ <= Tn - 1)  /* count each row exactly once */            \
                cnt += (int)(n_.x != 0.0f) + (int)(n_.y != 0.0f);            \
        }                                                                    \
        /* two PARALLEL 3-deep 32-bit extraction chains (tags 2j / 2j+1) */  \
        int e0 = 2 * (__ffs((int)m_ev) - 1);                                 \
        const unsigned me2 = m_ev & (m_ev - 1);                              \
        int e1 = me2 ? (2 * (__ffs((int)me2) - 1)) : e0;                     \
        const unsigned me3 = me2 & (me2 - 1);                                \
        int e2 = me3 ? (2 * (__ffs((int)me3) - 1)) : e1;                     \
        unsigned mrest_ev = me3 & (me3 - 1);                                 \
        int o0 = m_od ? (2 * (__ffs((int)m_od) - 1) + 1) : -1;               \
        const unsigned mo2 = m_od & (m_od - 1);                              \
        int o1 = mo2 ? (2 * (__ffs((int)mo2) - 1) + 1) : o0;                 \
        const unsigned mo3 = mo2 & (mo2 - 1);                                \
        int o2 = mo3 ? (2 * (__ffs((int)mo3) - 1) + 1) : o1;                 \
        unsigned mrest_od = mo3 & (mo3 - 1);                                 \
        if (!m_ev) { e0 = o0; e1 = o0; e2 = o0; }  /* pad: dup valid tag */  \
        if (!m_od) { o0 = e0; o1 = e0; o2 = e0; }  /* (both-empty imposs) */ \
        float sE0e, sE0o, sE1e, sE1o, sE2e, sE2o;                            \
        float sO0e, sO0o, sO1e, sO1o, sO2e, sO2o;                            \
        FETCH(e0, sE0e, sE0o); FETCH(e1, sE1e, sE1o); FETCH(e2, sE2e, sE2o); \
        FETCH(o0, sO0e, sO0o); FETCH(o1, sO1e, sO1o); FETCH(o2, sO2e, sO2o); \
        /* per-half FMNMX trees (best is bitwise one of the candidates) */   \
        const float mev0 = fmaxf(fmaxf(sE0e, sE1e), sE2e);                   \
        const float mod0 = fmaxf(fmaxf(sO0e, sO1e), sO2e);                   \
        const float mev1 = fmaxf(fmaxf(sE0o, sE1o), sE2o);                   \
        const float mod1 = fmaxf(fmaxf(sO0o, sO1o), sO2o);                   \
        float best0 = fmaxf(mev0, mod0);                                     \
        float best1 = fmaxf(mev1, mod1);                                     \
        /* per-half ordered recovery (ascending in half, smallest last) */   \
        int re0 = e2, ro0 = o2, re1 = e2, ro1 = o2;                          \
        re0 = (sE1e == mev0) ? e1 : re0;  re1 = (sE1o == mev1) ? e1 : re1;   \
        re0 = (sE0e == mev0) ? e0 : re0;  re1 = (sE0o == mev1) ? e0 : re1;   \
        ro0 = (sO1e == mod0) ? o1 : ro0;  ro1 = (sO1o == mod1) ? o1 : ro1;   \
        ro0 = (sO0e == mod0) ? o0 : ro0;  ro1 = (sO0o == mod1) ? o0 : ro1;   \
        /* cross-half min-select: smallest tag among global value-ties */    \
        int bi0, bi1;                                                        \
        {                                                                    \
            const int be = (mev0 == best0) ? re0 : 255;                      \
            const int bo = (mod0 == best0) ? ro0 : 255;                      \
            bi0 = min(be, bo);                                               \
        }                                                                    \
        {                                                                    \
            const int be = (mev1 == best1) ? re1 : 255;                      \
            const int bo = (mod1 == best1) ? ro1 : 255;                      \
            bi1 = min(be, bo);                                               \
        }                                                                    \
        if (mrest_ev | mrest_od) { /* rare: exact, index-aware tie-break */  \
            while (mrest_ev) {                                               \
                const int i_ = 2 * (__ffs((int)mrest_ev) - 1);               \
                mrest_ev &= mrest_ev - 1;                                    \
                float se_, so_;                                              \
                FETCH(i_, se_, so_);                                         \
                { const bool g = (se_ > best0) ||                            \
                                 (se_ == best0 && i_ < bi0);                 \
                  best0 = g ? se_ : best0;  bi0 = g ? i_ : bi0; }            \
                { const bool g = (so_ > best1) ||                            \
                                 (so_ == best1 && i_ < bi1);                 \
                  best1 = g ? so_ : best1;  bi1 = g ? i_ : bi1; }            \
            }                                                                \
            while (mrest_od) {                                               \
                const int i_ = 2 * (__ffs((int)mrest_od) - 1) + 1;           \
                mrest_od &= mrest_od - 1;                                    \
                float se_, so_;                                              \
                FETCH(i_, se_, so_);                                         \
                { const bool g = (se_ > best0) ||                            \
                                 (se_ == best0 && i_ < bi0);                 \
                  best0 = g ? se_ : best0;  bi0 = g ? i_ : bi0; }            \
                { const bool g = (so_ > best1) ||                            \
                                 (so_ == best1 && i_ < bi1);                 \
                  best1 = g ? so_ : best1;  bi1 = g ? i_ : bi1; }            \
            }                                                                \
        }                                                                    \
        a.x = p_.x + best0;                                                  \
        a.y = p_.y + best1;                                                  \
        /* packed backpointer store: one STS.16 per lane */                  \
        bp16[(t_ - 1) * 32 + l] =                                            \
            (unsigned short)((unsigned)bi0 | ((unsigned)bi1 << 8));          \
        /* EXACT threshold for the next step (proven R8 form) */             \
        const unsigned am_ = fmap(a.x), ah_ = fmap(a.y);                     \
        const unsigned wm_ =                                                 \
            __reduce_max_sync(0xffffffffu, am_ > ah_ ? am_ : ah_);           \
        const float thr_ = funmap(wm_) - rTp;                                \
        m_ev = __ballot_sync(0xffffffffu, a.x >= thr_);                      \
        m_od = __ballot_sync(0xffffffffu, a.y >= thr_);                      \
    }

// ---------------------------------------------------------------------------
// Single-warp Viterbi: even/odd ownership, exact-threshold pruning, fused
// seq-len count with speculative fast path + exact redo.
// ---------------------------------------------------------------------------
__global__ __launch_bounds__(32) void viterbi_kernel(
    const float* __restrict__ pots,   // [B, T, K]
    const float* __restrict__ trans,  // [K, K]
    float* __restrict__ out)          // [B, T] float32
{
    extern __shared__ float2 trans2[];              // [64][32]: (T[i][2l], T[i][2l+1])
    __shared__ unsigned short bp16[(Tn - 1) * 32];  // packed (bi_ev | bi_od<<8)
    __shared__ unsigned char tags[Tn];
    __shared__ __align__(8) float alpha_f[Kn];

    const int b = blockIdx.x;
    const int l = threadIdx.x;  // lane; owns tags 2l and 2l+1

    // ---- Prologue: stage transitions (even/odd float2) + padded range ----
    const float4* tr4 = (const float4*)trans;
    float tmin = FLT_MAX, tmax = -FLT_MAX;
#pragma unroll
    for (int q = 0; q < 32; q++) {
        const int idx = q * 32 + l;
        const float4 v = tr4[idx];
        tmin = fminf(tmin, fminf(fminf(v.x, v.y), fminf(v.z, v.w)));
        tmax = fmaxf(tmax, fmaxf(fmaxf(v.x, v.y), fmaxf(v.z, v.w)));
        const int i = idx >> 4;            // from-tag
        const int jb = (idx & 15) * 4;     // first to-tag (even)
        trans2[i * 32 + (jb >> 1)]     = make_float2(v.x, v.y);
        trans2[i * 32 + (jb >> 1) + 1] = make_float2(v.z, v.w);
    }
    const unsigned rmn = __reduce_min_sync(0xffffffffu, fmap(tmin));
    const unsigned rmx = __reduce_max_sync(0xffffffffu, fmap(tmax));
    const float r = funmap(rmx) - funmap(rmn);
    const float rTp = r + fabsf(r) * 1e-5f + 0.01f;  // pad only ADDS candidates
    __syncwarp();

    const float2* pb2 = (const float2*)(pots + (size_t)b * Tn * Kn);
    int cnt = 0;  // per-lane nonzero count (each row touched exactly once)

    float2 a = pb2[l];  // alpha0 (tags 2l, 2l+1)
    cnt += (int)(a.x != 0.0f) + (int)(a.y != 0.0f);  // row 0

    // ---------------- SPECULATIVE FAST PATH (assume sl == Tn) --------------
    unsigned m_ev, m_od;
    {
        const unsigned am = fmap(a.x), ah = fmap(a.y);
        const unsigned wm = __reduce_max_sync(0xffffffffu, am > ah ? am : ah);
        const float thr = funmap(wm) - rTp;
        m_ev = __ballot_sync(0xffffffffu, a.x >= thr);
        m_od = __ballot_sync(0xffffffffu, a.y >= thr);
    }
    float2 pr[PD];
#pragma unroll
    for (int d = 1; d <= PD; d++) {  // rows 1..PD counted here
        const float2 n = pb2[d * 32 + l];
        pr[d & (PD - 1)] = n;
        cnt += (int)(n.x != 0.0f) + (int)(n.y != 0.0f);
    }
    {
        int t = 1;
#pragma unroll 1
        for (int tb = 0; tb < 63; tb++) {
            STEP_F(t + 0, 1); STEP_F(t + 1, 2); STEP_F(t + 2, 3); STEP_F(t + 3, 4);
            STEP_F(t + 4, 5); STEP_F(t + 5, 6); STEP_F(t + 6, 7); STEP_F(t + 7, 0);
            t += 8;
        }
        STEP_F(t + 0, 1); STEP_F(t + 1, 2); STEP_F(t + 2, 3); STEP_F(t + 3, 4);
        STEP_F(t + 4, 5); STEP_F(t + 5, 6); STEP_F(t + 6, 7);
    }

    // ---- Verify speculation: exact seq_len from the fused count ----
    const int total = __reduce_add_sync(0xffffffffu, cnt);
    const int sl = total >> 6;  // floor(mean over K=64), exact

    if (sl < Tn) {
        // -------- RARE EXACT REDO: general path with mask semantics --------
        a = pb2[l];
#pragma unroll 1
        for (int t = 1; t < Tn; t++) {
            if (t < sl) {
                float best0, best1; int bi0, bi1;
                full_scan64(a.x, a.y, trans2, l, best0, best1, bi0, bi1);
                const float2 p = pb2[t * 32 + l];
                a.x = p.x + best0;
                a.y = p.y + best1;
                bp16[(t - 1) * 32 + l] =
                    (unsigned short)((unsigned)bi0 | ((unsigned)bi1 << 8));
            } else {
                bp16[(t - 1) * 32 + l] =
                    (unsigned short)((unsigned)(2 * l) | ((unsigned)(2 * l + 1) << 8));
            }
        }
    }

    // Final alpha -> smem for the backtrace scan (vectorized write)
    ((float2*)alpha_f)[l] = a;
    __syncwarp();

    // Backtrace (smem pointer-chase) by lane 0. First max wins.
    if (l == 0) {
        float bv = alpha_f[0];
        int bt = 0;
#pragma unroll 1
        for (int i = 1; i < Kn; i++) {
            const float v = alpha_f[i];
            if (v > bv) { bv = v; bt = i; }
        }
        int tg = bt;
        tags[Tn - 1] = (unsigned char)tg;
#pragma unroll 1
        for (int tt = Tn - 2; tt >= 0; tt--) {
            const unsigned v = bp16[tt * 32 + (tg >> 1)];
            tg = (int)((v >> ((tg & 1) * 8)) & 0xffu);
            tags[tt] = (unsigned char)tg;
        }
    }
    __syncwarp();

    // Coalesced float32 output write (16 per lane).
    float* ob = out + (size_t)b * Tn;
#pragma unroll
    for (int tt = l; tt < Tn; tt += 32) ob[tt] = (float)tags[tt];
}

// ---------------------------------------------------------------------------
extern "C" void kernel_launch(void* const* d_in, const int* in_sizes, int n_in,
                              void* d_out, int out_size) {
    const float* inputs = nullptr;
    const float* transitions = nullptr;
    for (int i = 0; i < n_in; i++) {
        if (in_sizes[i] == Kn * Kn) transitions = (const float*)d_in[i];
        else if (in_sizes[i] == Bn * Tn * Kn) inputs = (const float*)d_in[i];
    }
    if (!inputs) inputs = (const float*)d_in[0];
    if (!transitions) transitions = (const float*)d_in[1];

    float* out = (float*)d_out;

    // Static (~17.6 KB) + 16 KB dynamic -> opt in (host config, capture-safe).
    cudaFuncSetAttribute(viterbi_kernel,
                         cudaFuncAttributeMaxDynamicSharedMemorySize,
                         Kn * 32 * (int)sizeof(float2));

    viterbi_kernel<<<Bn, 32, Kn * 32 * sizeof(float2)>>>(inputs, transitions, out);
}